// round 1
// baseline (speedup 1.0000x reference)
#include <cuda_runtime.h>
#include <cstdint>

// Problem constants
#define GRP 8
#define FID 64
#define FOD 64
#define HW  4096
#define CHN 512   // GRP*FID

// Transposed weights: [g][fi][f]
__device__ __align__(16) float g_wt[GRP * FID * FOD];

__global__ void transpose_w_kernel(const float* __restrict__ w) {
    int idx = blockIdx.x * 256 + threadIdx.x;   // 0..32767, fi fastest -> coalesced read
    int g  = idx >> 12;
    int f  = (idx >> 6) & 63;
    int fi = idx & 63;
    g_wt[(g * 64 + fi) * 64 + f] = w[idx];      // w[(g*64+f)*64+fi] == w[idx]
}

__device__ __forceinline__ unsigned smem_u32(const void* p) {
    return (unsigned)__cvta_generic_to_shared(p);
}
__device__ __forceinline__ void cp16(void* dst, const void* src) {
    asm volatile("cp.async.cg.shared.global [%0], [%1], 16;\n"
                 :: "r"(smem_u32(dst)), "l"(src));
}
__device__ __forceinline__ void cp_commit() {
    asm volatile("cp.async.commit_group;\n");
}
__device__ __forceinline__ void cp_wait_all() {
    asm volatile("cp.async.wait_group 0;\n");
}

// Block: 256 threads, 64 positions (one batch b, 64 contiguous hw).
// Thread: fcol = tid&7 (covers f = fcol*8 .. fcol*8+7), prow = tid>>3 (positions prow*2, prow*2+1).
// Warp: lanes = 8 fcols x 4 prows  ->  f-reduction = 3-round shfl butterfly over lane bits 0..2.
__global__ __launch_bounds__(256, 1)
void routing_kernel(const float* __restrict__ x,
                    const float* __restrict__ bias,
                    float* __restrict__ out) {
    extern __shared__ float smem[];
    float* w_s = smem;           // 2 bufs x 64fi x 64f  = 8192 floats
    float* x_s = smem + 8192;    // 2 bufs x 64fi x 64p  = 8192 floats

    const int tid  = threadIdx.x;
    const int fcol = tid & 7;
    const int prow = tid >> 3;                 // 0..31
    const int b    = blockIdx.x >> 6;
    const int base_hw = (blockIdx.x & 63) * 64;

    const float* xb = x + (size_t)b * CHN * HW + base_hw;

    // ---- stage group 0 into buffer 0 ----
    #pragma unroll
    for (int c = 0; c < 4; c++) {
        int chunk = tid + 256 * c;             // 0..1023 (16B chunks)
        int fi = chunk >> 4;
        int pc = (chunk & 15) * 4;
        cp16(&x_s[fi * 64 + pc], xb + (size_t)fi * HW + pc);
        cp16(&w_s[fi * 64 + pc], &g_wt[fi * 64 + pc]);
    }
    cp_commit();
    cp_wait_all();
    __syncthreads();

    float con[8][8][2];
    #pragma unroll
    for (int g = 0; g < 8; g++)
        #pragma unroll
        for (int j = 0; j < 8; j++) {
            con[g][j][0] = 0.0f;
            con[g][j][1] = 0.0f;
        }

    // ---- fused grouped 1x1 conv: con[g][f][p] = sum_fi W[g][f][fi] * x[g][fi][p] ----
    #pragma unroll
    for (int g = 0; g < 8; g++) {
        const int buf  = (g & 1) * 4096;
        if (g < 7) {
            const int nbuf = ((g + 1) & 1) * 4096;
            #pragma unroll
            for (int c = 0; c < 4; c++) {
                int chunk = tid + 256 * c;
                int fi = chunk >> 4;
                int pc = (chunk & 15) * 4;
                cp16(&x_s[nbuf + fi * 64 + pc],
                     xb + (size_t)((g + 1) * 64 + fi) * HW + pc);
                cp16(&w_s[nbuf + fi * 64 + pc],
                     &g_wt[((g + 1) * 64 + fi) * 64 + pc]);
            }
            cp_commit();
        }

        const float* wsb = &w_s[buf];
        const float* xsb = &x_s[buf];
        #pragma unroll 4
        for (int fi = 0; fi < 64; fi++) {
            float2 xv = *reinterpret_cast<const float2*>(&xsb[fi * 64 + prow * 2]);
            float4 wa = *reinterpret_cast<const float4*>(&wsb[fi * 64 + fcol * 8]);
            float4 wb = *reinterpret_cast<const float4*>(&wsb[fi * 64 + fcol * 8 + 4]);
            float wv[8] = {wa.x, wa.y, wa.z, wa.w, wb.x, wb.y, wb.z, wb.w};
            #pragma unroll
            for (int j = 0; j < 8; j++) {
                con[g][j][0] = fmaf(wv[j], xv.x, con[g][j][0]);
                con[g][j][1] = fmaf(wv[j], xv.y, con[g][j][1]);
            }
        }

        if (g < 7) {
            cp_wait_all();
            __syncthreads();
        }
    }

    // ---- dynamic routing (3 iterations), all in registers ----
    float beta[8][2];
    #pragma unroll
    for (int g = 0; g < 8; g++) { beta[g][0] = 0.0f; beta[g][1] = 0.0f; }

    float v[8][2];

    #pragma unroll
    for (int it = 0; it < 3; it++) {
        float alpha[8][2];
        #pragma unroll
        for (int g = 0; g < 8; g++)
            #pragma unroll
            for (int k = 0; k < 2; k++)
                alpha[g][k] = 1.0f / (1.0f + __expf(-beta[g][k]));

        // v[f][p] = sum_g alpha[g][p] * con[g][f][p]
        #pragma unroll
        for (int j = 0; j < 8; j++)
            #pragma unroll
            for (int k = 0; k < 2; k++) {
                float acc = 0.0f;
                #pragma unroll
                for (int g = 0; g < 8; g++)
                    acc = fmaf(alpha[g][k], con[g][j][k], acc);
                v[j][k] = acc;
            }

        if (it == 2) break;

        // beta[g][p] += sum over ALL f of v[f][p]*con[g][f][p]
        // local partial over this thread's 8 f, then butterfly over 8 fcol lanes.
        #pragma unroll
        for (int g = 0; g < 8; g++)
            #pragma unroll
            for (int k = 0; k < 2; k++) {
                float p = 0.0f;
                #pragma unroll
                for (int j = 0; j < 8; j++)
                    p = fmaf(v[j][k], con[g][j][k], p);
                #pragma unroll
                for (int m = 1; m < 8; m <<= 1)
                    p += __shfl_xor_sync(0xffffffffu, p, m);
                beta[g][k] += p;
            }
    }

    // ---- epilogue: transpose v through smem for coalesced stores ----
    __syncthreads();                   // everyone past conv: safe to reuse x_s
    float* v_s = x_s;                  // 64 f x stride 66 = 4224 floats (< 8192)
    #pragma unroll
    for (int j = 0; j < 8; j++) {
        int f = fcol * 8 + j;
        v_s[f * 66 + prow * 2]     = v[j][0];
        v_s[f * 66 + prow * 2 + 1] = v[j][1];
    }
    __syncthreads();

    float* outb = out + (size_t)b * 64 * HW + base_hw;
    #pragma unroll
    for (int c = 0; c < 16; c++) {
        int flat = tid + 256 * c;      // 0..4095
        int f = flat >> 6;
        int p = flat & 63;
        outb[(size_t)f * HW + p] = v_s[f * 66 + p] + __ldg(&bias[f]);
    }
}

extern "C" void kernel_launch(void* const* d_in, const int* in_sizes, int n_in,
                              void* d_out, int out_size) {
    const float* x    = (const float*)d_in[0];
    const float* w    = (const float*)d_in[1];
    const float* bias = (const float*)d_in[2];
    float* out = (float*)d_out;

    transpose_w_kernel<<<128, 256>>>(w);

    cudaFuncSetAttribute(routing_kernel,
                         cudaFuncAttributeMaxDynamicSharedMemorySize, 65536);
    routing_kernel<<<1024, 256, 65536>>>(x, bias, out);
}

// round 2
// speedup vs baseline: 1.0003x; 1.0003x over previous
#include <cuda_runtime.h>
#include <cstdint>

// Problem constants
#define GRP 8
#define FID 64
#define FOD 64
#define HW  4096
#define CHN 512   // GRP*FID

// Transposed weights: [g][fi][f]
__device__ __align__(16) float g_wt[GRP * FID * FOD];

__global__ void transpose_w_kernel(const float* __restrict__ w) {
    int idx = blockIdx.x * 256 + threadIdx.x;   // 0..32767, fi fastest -> coalesced read
    int g  = idx >> 12;
    int f  = (idx >> 6) & 63;
    int fi = idx & 63;
    g_wt[(g * 64 + fi) * 64 + f] = w[idx];      // w[(g*64+f)*64+fi] == w[idx]
}

__device__ __forceinline__ unsigned smem_u32(const void* p) {
    return (unsigned)__cvta_generic_to_shared(p);
}
__device__ __forceinline__ void cp16(void* dst, const void* src) {
    asm volatile("cp.async.cg.shared.global [%0], [%1], 16;\n"
                 :: "r"(smem_u32(dst)), "l"(src));
}
__device__ __forceinline__ void cp_commit() {
    asm volatile("cp.async.commit_group;\n");
}
__device__ __forceinline__ void cp_wait_all() {
    asm volatile("cp.async.wait_group 0;\n");
}

// Block: 256 threads, 64 positions (one batch b, 64 contiguous hw).
// Thread: fcol = tid&7 (covers f = fcol*8 .. fcol*8+7), prow = tid>>3 (positions prow*2, prow*2+1).
// Warp: lanes = 8 fcols x 4 prows  ->  f-reduction = 3-round shfl butterfly over lane bits 0..2.
__global__ __launch_bounds__(256, 1)
void routing_kernel(const float* __restrict__ x,
                    const float* __restrict__ bias,
                    float* __restrict__ out) {
    extern __shared__ float smem[];
    float* w_s = smem;           // 2 bufs x 64fi x 64f  = 8192 floats
    float* x_s = smem + 8192;    // 2 bufs x 64fi x 64p  = 8192 floats

    const int tid  = threadIdx.x;
    const int fcol = tid & 7;
    const int prow = tid >> 3;                 // 0..31
    const int b    = blockIdx.x >> 6;
    const int base_hw = (blockIdx.x & 63) * 64;

    const float* xb = x + (size_t)b * CHN * HW + base_hw;

    // ---- stage group 0 into buffer 0 ----
    #pragma unroll
    for (int c = 0; c < 4; c++) {
        int chunk = tid + 256 * c;             // 0..1023 (16B chunks)
        int fi = chunk >> 4;
        int pc = (chunk & 15) * 4;
        cp16(&x_s[fi * 64 + pc], xb + (size_t)fi * HW + pc);
        cp16(&w_s[fi * 64 + pc], &g_wt[fi * 64 + pc]);
    }
    cp_commit();
    cp_wait_all();
    __syncthreads();

    float con[8][8][2];
    #pragma unroll
    for (int g = 0; g < 8; g++)
        #pragma unroll
        for (int j = 0; j < 8; j++) {
            con[g][j][0] = 0.0f;
            con[g][j][1] = 0.0f;
        }

    // ---- fused grouped 1x1 conv: con[g][f][p] = sum_fi W[g][f][fi] * x[g][fi][p] ----
    #pragma unroll
    for (int g = 0; g < 8; g++) {
        const int buf  = (g & 1) * 4096;
        if (g < 7) {
            const int nbuf = ((g + 1) & 1) * 4096;
            #pragma unroll
            for (int c = 0; c < 4; c++) {
                int chunk = tid + 256 * c;
                int fi = chunk >> 4;
                int pc = (chunk & 15) * 4;
                cp16(&x_s[nbuf + fi * 64 + pc],
                     xb + (size_t)((g + 1) * 64 + fi) * HW + pc);
                cp16(&w_s[nbuf + fi * 64 + pc],
                     &g_wt[((g + 1) * 64 + fi) * 64 + pc]);
            }
            cp_commit();
        }

        const float* wsb = &w_s[buf];
        const float* xsb = &x_s[buf];
        #pragma unroll 4
        for (int fi = 0; fi < 64; fi++) {
            float2 xv = *reinterpret_cast<const float2*>(&xsb[fi * 64 + prow * 2]);
            float4 wa = *reinterpret_cast<const float4*>(&wsb[fi * 64 + fcol * 8]);
            float4 wb = *reinterpret_cast<const float4*>(&wsb[fi * 64 + fcol * 8 + 4]);
            float wv[8] = {wa.x, wa.y, wa.z, wa.w, wb.x, wb.y, wb.z, wb.w};
            #pragma unroll
            for (int j = 0; j < 8; j++) {
                con[g][j][0] = fmaf(wv[j], xv.x, con[g][j][0]);
                con[g][j][1] = fmaf(wv[j], xv.y, con[g][j][1]);
            }
        }

        if (g < 7) {
            cp_wait_all();
            __syncthreads();
        }
    }

    // ---- dynamic routing (3 iterations), all in registers ----
    float beta[8][2];
    #pragma unroll
    for (int g = 0; g < 8; g++) { beta[g][0] = 0.0f; beta[g][1] = 0.0f; }

    float v[8][2];

    #pragma unroll
    for (int it = 0; it < 3; it++) {
        float alpha[8][2];
        #pragma unroll
        for (int g = 0; g < 8; g++)
            #pragma unroll
            for (int k = 0; k < 2; k++)
                alpha[g][k] = 1.0f / (1.0f + __expf(-beta[g][k]));

        // v[f][p] = sum_g alpha[g][p] * con[g][f][p]
        #pragma unroll
        for (int j = 0; j < 8; j++)
            #pragma unroll
            for (int k = 0; k < 2; k++) {
                float acc = 0.0f;
                #pragma unroll
                for (int g = 0; g < 8; g++)
                    acc = fmaf(alpha[g][k], con[g][j][k], acc);
                v[j][k] = acc;
            }

        if (it == 2) break;

        // beta[g][p] += sum over ALL f of v[f][p]*con[g][f][p]
        // local partial over this thread's 8 f, then butterfly over 8 fcol lanes.
        #pragma unroll
        for (int g = 0; g < 8; g++)
            #pragma unroll
            for (int k = 0; k < 2; k++) {
                float p = 0.0f;
                #pragma unroll
                for (int j = 0; j < 8; j++)
                    p = fmaf(v[j][k], con[g][j][k], p);
                #pragma unroll
                for (int m = 1; m < 8; m <<= 1)
                    p += __shfl_xor_sync(0xffffffffu, p, m);
                beta[g][k] += p;
            }
    }

    // ---- epilogue: transpose v through smem for coalesced stores ----
    __syncthreads();                   // everyone past conv: safe to reuse x_s
    float* v_s = x_s;                  // 64 f x stride 66 = 4224 floats (< 8192)
    #pragma unroll
    for (int j = 0; j < 8; j++) {
        int f = fcol * 8 + j;
        v_s[f * 66 + prow * 2]     = v[j][0];
        v_s[f * 66 + prow * 2 + 1] = v[j][1];
    }
    __syncthreads();

    float* outb = out + (size_t)b * 64 * HW + base_hw;
    #pragma unroll
    for (int c = 0; c < 16; c++) {
        int flat = tid + 256 * c;      // 0..4095
        int f = flat >> 6;
        int p = flat & 63;
        outb[(size_t)f * HW + p] = v_s[f * 66 + p] + __ldg(&bias[f]);
    }
}

extern "C" void kernel_launch(void* const* d_in, const int* in_sizes, int n_in,
                              void* d_out, int out_size) {
    const float* x    = (const float*)d_in[0];
    const float* w    = (const float*)d_in[1];
    const float* bias = (const float*)d_in[2];
    float* out = (float*)d_out;

    transpose_w_kernel<<<128, 256>>>(w);

    cudaFuncSetAttribute(routing_kernel,
                         cudaFuncAttributeMaxDynamicSharedMemorySize, 65536);
    routing_kernel<<<1024, 256, 65536>>>(x, bias, out);
}

// round 4
// speedup vs baseline: 2.5337x; 2.5329x over previous
#include <cuda_runtime.h>
#include <cuda_bf16.h>
#include <cstdint>

#define HW 4096
#define CHN 512

// smem byte offsets (dynamic)
#define OFF_XRAW 0          // 2 x 16384 : raw x tile [64 fi][64 p] fp32
#define OFF_A    32768      // 2 x 16384 : A[p][fi] bf16, hi 8KB + lo 8KB, swizzled
#define OFF_B    65536      // 2 x 16384 : B[f][fi] bf16, hi 8KB + lo 8KB, swizzled
#define SMEM_TOTAL 98304

#define SWZ_ROW(r) (((uint32_t)(r) & 7u) << 4)

// pre-split, pre-swizzled weights: per group 2048 u32 (hi image) + 2048 u32 (lo image)
__device__ __align__(16) unsigned g_bw[8 * 4096];

__global__ void prep_kernel(const float* __restrict__ w) {
    int idx = blockIdx.x * 256 + threadIdx.x;     // 0..16383, one fi-pair each
    int g   = idx >> 11;
    int f   = (idx >> 5) & 63;
    int fi2 = idx & 31;                           // fi = 2*fi2
    const float* src = w + ((size_t)(g * 64 + f) * 64 + fi2 * 2);
    float v0 = src[0], v1 = src[1];
    uint32_t hw_, lw_;
    asm("cvt.rn.bf16x2.f32 %0, %1, %2;" : "=r"(hw_) : "f"(v1), "f"(v0));
    float h0 = __uint_as_float(hw_ << 16);
    float h1 = __uint_as_float(hw_ & 0xffff0000u);
    float l0 = v0 - h0, l1 = v1 - h1;
    asm("cvt.rn.bf16x2.f32 %0, %1, %2;" : "=r"(lw_) : "f"(l1), "f"(l0));
    uint32_t o  = (uint32_t)(f * 128 + fi2 * 4);
    uint32_t wi = (o ^ SWZ_ROW(f)) >> 2;
    g_bw[g * 4096 + wi]        = hw_;
    g_bw[g * 4096 + 2048 + wi] = lw_;
}

__device__ __forceinline__ void cp16(uint32_t dst, const void* src) {
    asm volatile("cp.async.cg.shared.global [%0], [%1], 16;\n" :: "r"(dst), "l"(src));
}
__device__ __forceinline__ void cp_commit() { asm volatile("cp.async.commit_group;\n"); }

#define LDSM4(r, addr) asm volatile( \
    "ldmatrix.sync.aligned.m8n8.x4.shared.b16 {%0,%1,%2,%3}, [%4];\n" \
    : "=r"((r)[0]), "=r"((r)[1]), "=r"((r)[2]), "=r"((r)[3]) : "r"(addr))

#define MMA(d, a, b) asm volatile( \
    "mma.sync.aligned.m16n8k16.row.col.f32.bf16.bf16.f32 " \
    "{%0,%1,%2,%3}, {%4,%5,%6,%7}, {%8,%9}, {%0,%1,%2,%3};\n" \
    : "+f"((d)[0]), "+f"((d)[1]), "+f"((d)[2]), "+f"((d)[3]) \
    : "r"((a)[0]), "r"((a)[1]), "r"((a)[2]), "r"((a)[3]), "r"((b)[0]), "r"((b)[1]))

__device__ __forceinline__ float sigmoidf_(float x) { return 1.0f / (1.0f + __expf(-x)); }

__global__ __launch_bounds__(256, 1)
void routing_kernel(const float* __restrict__ x,
                    const float* __restrict__ bias,
                    float* __restrict__ out) {
    extern __shared__ char smem[];
    const uint32_t sb = (uint32_t)__cvta_generic_to_shared(smem);
    const int tid  = threadIdx.x;
    const int lane = tid & 31;
    const int wid  = tid >> 5;
    const int warp_m = wid >> 1;          // position quad: rows [warp_m*16, +16)
    const int warp_n = wid & 1;           // f half: [warp_n*32, +32)
    const int b   = blockIdx.x >> 6;
    const int hw0 = (blockIdx.x & 63) * 64;
    const float* xb = x + (size_t)b * CHN * HW + hw0;

    // ---------- staging ----------
    auto load_x = [&](int g, int buf) {
        #pragma unroll
        for (int c = 0; c < 4; c++) {
            int ch = tid + 256 * c;                  // 0..1023 16B chunks
            int fi = ch >> 4, p4 = (ch & 15) * 4;
            cp16(sb + (uint32_t)(OFF_XRAW + buf * 16384 + ch * 16),
                 xb + (size_t)(g * 64 + fi) * HW + p4);
        }
    };
    auto load_b = [&](int g, int buf) {
        const unsigned* src = g_bw + g * 4096;
        #pragma unroll
        for (int c = 0; c < 4; c++) {
            int ch = tid + 256 * c;
            cp16(sb + (uint32_t)(OFF_B + buf * 16384 + ch * 16), src + ch * 4);
        }
    };
    // transpose + bf16 hi/lo split: XRAW[fi][p] -> A[p][fi] (swizzled 128B rows)
    auto convert = [&](int buf) {
        const float* xr = (const float*)(smem + OFF_XRAW + buf * 16384);
        char* Ah = smem + OFF_A + buf * 16384;
        int p  = tid & 63;
        int fg = tid >> 6;                           // fi block of 16
        uint32_t rowterm = (uint32_t)(p * 128);
        uint32_t sw = SWZ_ROW(p);
        #pragma unroll
        for (int q = 0; q < 8; q++) {
            int fi = fg * 16 + q * 2;
            float v0 = xr[fi * 64 + p];
            float v1 = xr[(fi + 1) * 64 + p];
            uint32_t hw_, lw_;
            asm("cvt.rn.bf16x2.f32 %0, %1, %2;" : "=r"(hw_) : "f"(v1), "f"(v0));
            float h0 = __uint_as_float(hw_ << 16);
            float h1 = __uint_as_float(hw_ & 0xffff0000u);
            float l0 = v0 - h0, l1 = v1 - h1;
            asm("cvt.rn.bf16x2.f32 %0, %1, %2;" : "=r"(lw_) : "f"(l1), "f"(l0));
            uint32_t off = (rowterm + (uint32_t)(fi * 2)) ^ sw;
            *(uint32_t*)(Ah + off)        = hw_;
            *(uint32_t*)(Ah + 8192 + off) = lw_;
        }
    };

    // ---------- per-lane ldmatrix address components ----------
    const int q  = lane >> 3;
    const int r8 = lane & 7;
    // A: lane supplies row r of tile q: tiles (m0-7,k0),(m8-15,k0),(m0-7,k8),(m8-15,k8)
    const uint32_t a_row  = (uint32_t)(warp_m * 16 + (q & 1) * 8 + r8);
    const uint32_t a_rt   = a_row * 128;
    const uint32_t a_sw   = SWZ_ROW(a_row);
    const uint32_t a_colq = (uint32_t)((q >> 1) * 16);
    // B: load u covers n-tiles 2u,2u+1 ; tiles (n0,k0),(n0,k8),(n1,k0),(n1,k8)
    const uint32_t b_sw   = SWZ_ROW(r8);
    const uint32_t b_colq = (uint32_t)((q & 1) * 16);
    uint32_t b_rt[2];
    #pragma unroll
    for (int u = 0; u < 2; u++)
        b_rt[u] = (uint32_t)((warp_n * 32 + (2 * u + (q >> 1)) * 8 + r8) * 128);

    float con[8][4][4];
    #pragma unroll
    for (int g = 0; g < 8; g++)
        #pragma unroll
        for (int nt = 0; nt < 4; nt++)
            #pragma unroll
            for (int k = 0; k < 4; k++) con[g][nt][k] = 0.0f;

    // ---------- prologue ----------
    load_x(0, 0); load_b(0, 0); cp_commit();
    load_x(1, 1); load_b(1, 1); cp_commit();
    asm volatile("cp.async.wait_group 1;\n");
    __syncthreads();
    convert(0);
    __syncthreads();

    // ---------- pipelined group loop ----------
    #pragma unroll
    for (int g = 0; g < 8; g++) {
        const int buf = g & 1;
        const uint32_t Ah = sb + OFF_A + buf * 16384, Al = Ah + 8192;
        const uint32_t Bh = sb + OFF_B + buf * 16384, Bl = Bh + 8192;
        #pragma unroll
        for (int kk = 0; kk < 4; kk++) {
            uint32_t acol = ((uint32_t)(kk * 32) + a_colq) ^ a_sw;
            uint32_t bcol = ((uint32_t)(kk * 32) + b_colq) ^ b_sw;
            uint32_t ah[4], al[4], bh[8], bl[8];
            LDSM4(ah, Ah + a_rt + acol);
            LDSM4(al, Al + a_rt + acol);
            LDSM4(&bh[0], Bh + b_rt[0] + bcol);
            LDSM4(&bh[4], Bh + b_rt[1] + bcol);
            LDSM4(&bl[0], Bl + b_rt[0] + bcol);
            LDSM4(&bl[4], Bl + b_rt[1] + bcol);
            #pragma unroll
            for (int nt = 0; nt < 4; nt++) {
                MMA(con[g][nt], ah, &bh[nt * 2]);
                MMA(con[g][nt], ah, &bl[nt * 2]);
                MMA(con[g][nt], al, &bh[nt * 2]);
            }
        }
        if (g < 7) {
            asm volatile("cp.async.wait_group 0;\n");
            __syncthreads();                 // x/B(g+1) landed; all warps past mma(g)
            convert((g + 1) & 1);
            __syncthreads();
            if (g < 6) { load_x(g + 2, buf); load_b(g + 2, buf); cp_commit(); }
        }
    }

    // ================= routing epilogue =================
    float* sbuf = (float*)smem;                       // [2][64][36]
    float* abuf = (float*)(smem + 2 * 64 * 36 * 4);   // [64][9]
    const int r0 = warp_m * 16 + (lane >> 2);         // thread's first row (position)

    // Gram matrix S[g][g'] per row, partial over this warp's 8 f-cols
    #pragma unroll
    for (int rr = 0; rr < 2; rr++) {
        float S[36];
        int idx = 0;
        #pragma unroll
        for (int a = 0; a < 8; a++) {
            #pragma unroll
            for (int c = a; c < 8; c++, idx++) {
                float acc = 0.0f;
                #pragma unroll
                for (int nt = 0; nt < 4; nt++) {
                    acc = fmaf(con[a][nt][2 * rr],     con[c][nt][2 * rr],     acc);
                    acc = fmaf(con[a][nt][2 * rr + 1], con[c][nt][2 * rr + 1], acc);
                }
                S[idx] = acc;
            }
        }
        #pragma unroll
        for (int i = 0; i < 36; i++) {
            S[i] += __shfl_xor_sync(0xffffffffu, S[i], 1);
            S[i] += __shfl_xor_sync(0xffffffffu, S[i], 2);
        }
        int row = r0 + rr * 8;
        for (int i = (lane & 3); i < 36; i += 4)
            sbuf[(warp_n * 64 + row) * 36 + i] = S[i];
    }
    __syncthreads();

    // per-position recurrence (threads 0..63)
    if (tid < 64) {
        float Sf[36];
        #pragma unroll
        for (int i = 0; i < 36; i++)
            Sf[i] = sbuf[tid * 36 + i] + sbuf[(64 + tid) * 36 + i];
        auto SM = [&](int a, int c) -> float {
            int lo = a < c ? a : c, hi = a < c ? c : a;
            return Sf[lo * 8 - (lo * (lo + 1)) / 2 + hi];
        };
        float beta[8];
        #pragma unroll
        for (int g = 0; g < 8; g++) {          // iter 0: alpha = 0.5
            float rs = 0.0f;
            #pragma unroll
            for (int gp = 0; gp < 8; gp++) rs += SM(g, gp);
            beta[g] = 0.5f * rs;
        }
        float alpha[8];
        #pragma unroll
        for (int g = 0; g < 8; g++) alpha[g] = sigmoidf_(beta[g]);
        #pragma unroll
        for (int g = 0; g < 8; g++) {          // iter 1
            float acc = 0.0f;
            #pragma unroll
            for (int gp = 0; gp < 8; gp++) acc = fmaf(alpha[gp], SM(gp, g), acc);
            beta[g] += acc;
        }
        #pragma unroll
        for (int g = 0; g < 8; g++) abuf[tid * 9 + g] = sigmoidf_(beta[g]);
    }
    __syncthreads();

    // v = sum_g alpha_g * con_g
    float a0[8], a1[8];
    #pragma unroll
    for (int g = 0; g < 8; g++) {
        a0[g] = abuf[r0 * 9 + g];
        a1[g] = abuf[(r0 + 8) * 9 + g];
    }
    float v[4][4];
    #pragma unroll
    for (int nt = 0; nt < 4; nt++)
        #pragma unroll
        for (int k = 0; k < 4; k++) v[nt][k] = 0.0f;
    #pragma unroll
    for (int g = 0; g < 8; g++)
        #pragma unroll
        for (int nt = 0; nt < 4; nt++) {
            v[nt][0] = fmaf(a0[g], con[g][nt][0], v[nt][0]);
            v[nt][1] = fmaf(a0[g], con[g][nt][1], v[nt][1]);
            v[nt][2] = fmaf(a1[g], con[g][nt][2], v[nt][2]);
            v[nt][3] = fmaf(a1[g], con[g][nt][3], v[nt][3]);
        }

    // transpose through smem for coalesced stores (vbuf region disjoint from abuf/sbuf)
    float* vbuf = (float*)(smem + OFF_A);             // [64 f][65]
    const int cb = 2 * (lane & 3);
    #pragma unroll
    for (int nt = 0; nt < 4; nt++) {
        int f = warp_n * 32 + nt * 8 + cb;
        vbuf[f * 65 + r0]           = v[nt][0];
        vbuf[(f + 1) * 65 + r0]     = v[nt][1];
        vbuf[f * 65 + r0 + 8]       = v[nt][2];
        vbuf[(f + 1) * 65 + r0 + 8] = v[nt][3];
    }
    __syncthreads();

    float* ob = out + (size_t)b * 64 * HW + hw0;
    #pragma unroll
    for (int c = 0; c < 16; c++) {
        int flat = tid + 256 * c;                     // 0..4095
        int f = flat >> 6, p = flat & 63;
        ob[(size_t)f * HW + p] = vbuf[f * 65 + p] + __ldg(&bias[f]);
    }
}

extern "C" void kernel_launch(void* const* d_in, const int* in_sizes, int n_in,
                              void* d_out, int out_size) {
    const float* x    = (const float*)d_in[0];
    const float* w    = (const float*)d_in[1];
    const float* bias = (const float*)d_in[2];
    float* out = (float*)d_out;

    prep_kernel<<<64, 256>>>(w);

    cudaFuncSetAttribute(routing_kernel,
                         cudaFuncAttributeMaxDynamicSharedMemorySize, SMEM_TOTAL);
    routing_kernel<<<1024, 256, SMEM_TOTAL>>>(x, bias, out);
}

// round 5
// speedup vs baseline: 3.1744x; 1.2529x over previous
#include <cuda_runtime.h>
#include <cuda_bf16.h>
#include <cstdint>

#define HW 4096
#define CHN 512

// dynamic smem byte offsets
#define OFF_XR 0          // 2 bufs x 32768 : raw x [128 fi][64 p] fp32 (2 groups/stage)
#define OFF_A  65536      // 2 bufs x 32768 : per buf {g0 hi 8K, g0 lo 8K, g1 hi, g1 lo}, [fi][p] bf16 swizzled
#define OFF_B  131072     // 2 bufs x 32768 : per buf {g0 hi, g0 lo, g1 hi, g1 lo}, [f][fi] bf16 swizzled
#define SMEM_TOTAL 196608

#define SWZ_ROW(r) (((uint32_t)(r) & 7u) << 4)

// pre-split, pre-swizzled weights: per group 2048 u32 (hi image) + 2048 u32 (lo image)
__device__ __align__(16) unsigned g_bw[8 * 4096];

__global__ void prep_kernel(const float* __restrict__ w) {
    int idx = blockIdx.x * 256 + threadIdx.x;     // 0..16383, one fi-pair each
    int g   = idx >> 11;
    int f   = (idx >> 5) & 63;
    int fi2 = idx & 31;                           // fi = 2*fi2
    const float* src = w + ((size_t)(g * 64 + f) * 64 + fi2 * 2);
    float v0 = src[0], v1 = src[1];
    uint32_t hw_, lw_;
    asm("cvt.rn.bf16x2.f32 %0, %1, %2;" : "=r"(hw_) : "f"(v1), "f"(v0));
    float h0 = __uint_as_float(hw_ << 16);
    float h1 = __uint_as_float(hw_ & 0xffff0000u);
    float l0 = v0 - h0, l1 = v1 - h1;
    asm("cvt.rn.bf16x2.f32 %0, %1, %2;" : "=r"(lw_) : "f"(l1), "f"(l0));
    uint32_t o  = (uint32_t)(f * 128 + fi2 * 4);
    uint32_t wi = (o ^ SWZ_ROW(f)) >> 2;
    g_bw[g * 4096 + wi]        = hw_;
    g_bw[g * 4096 + 2048 + wi] = lw_;
}

__device__ __forceinline__ void cp16(uint32_t dst, const void* src) {
    asm volatile("cp.async.cg.shared.global [%0], [%1], 16;\n" :: "r"(dst), "l"(src));
}
__device__ __forceinline__ void cp_commit() { asm volatile("cp.async.commit_group;\n"); }

#define LDSM4(r, addr) asm volatile( \
    "ldmatrix.sync.aligned.m8n8.x4.shared.b16 {%0,%1,%2,%3}, [%4];\n" \
    : "=r"((r)[0]), "=r"((r)[1]), "=r"((r)[2]), "=r"((r)[3]) : "r"(addr))

#define LDSM4T(r, addr) asm volatile( \
    "ldmatrix.sync.aligned.m8n8.x4.trans.shared.b16 {%0,%1,%2,%3}, [%4];\n" \
    : "=r"((r)[0]), "=r"((r)[1]), "=r"((r)[2]), "=r"((r)[3]) : "r"(addr))

#define MMA(d, a, b) asm volatile( \
    "mma.sync.aligned.m16n8k16.row.col.f32.bf16.bf16.f32 " \
    "{%0,%1,%2,%3}, {%4,%5,%6,%7}, {%8,%9}, {%0,%1,%2,%3};\n" \
    : "+f"((d)[0]), "+f"((d)[1]), "+f"((d)[2]), "+f"((d)[3]) \
    : "r"((a)[0]), "r"((a)[1]), "r"((a)[2]), "r"((a)[3]), "r"((b)[0]), "r"((b)[1]))

__device__ __forceinline__ float sigmoidf_(float x) { return 1.0f / (1.0f + __expf(-x)); }

__global__ __launch_bounds__(256, 1)
void routing_kernel(const float* __restrict__ x,
                    const float* __restrict__ bias,
                    float* __restrict__ out) {
    extern __shared__ char smem[];
    const uint32_t sb = (uint32_t)__cvta_generic_to_shared(smem);
    const int tid  = threadIdx.x;
    const int lane = tid & 31;
    const int wid  = tid >> 5;
    const int warp_m = wid >> 1;          // position quad: rows [warp_m*16, +16)
    const int warp_n = wid & 1;           // f half: [warp_n*32, +32)
    const int b   = blockIdx.x >> 6;
    const int hw0 = (blockIdx.x & 63) * 64;
    const float* xb = x + (size_t)b * CHN * HW + hw0;

    // ---------- staging: one stage = 2 groups ----------
    auto load_stage = [&](int s, int buf) {
        #pragma unroll
        for (int c = 0; c < 8; c++) {
            int ch = tid + 256 * c;                 // 0..2047 16B chunks (32KB x)
            int fi = ch >> 4, p4 = (ch & 15) * 4;
            cp16(sb + (uint32_t)(OFF_XR + buf * 32768 + ch * 16),
                 xb + (size_t)(s * 128 + fi) * HW + p4);
        }
        const unsigned* src = g_bw + s * 2 * 4096;  // 2 groups of B images (32KB)
        #pragma unroll
        for (int c = 0; c < 8; c++) {
            int ch = tid + 256 * c;
            cp16(sb + (uint32_t)(OFF_B + buf * 32768 + ch * 16), src + ch * 4);
        }
    };
    // fp32 -> bf16 hi/lo, NO transpose: keep [fi][p], swizzled 128B rows
    auto convert = [&](int buf) {
        const float* xr = (const float*)(smem + OFF_XR + buf * 32768);
        char* Ab = smem + OFF_A + buf * 32768;
        #pragma unroll
        for (int c = 0; c < 8; c++) {
            int ch = tid + 256 * c;                 // 0..2047 float4s
            int fi128 = ch >> 4;
            int p4 = (ch & 15) * 4;
            float4 v = *(const float4*)(xr + fi128 * 64 + p4);
            uint32_t h01, h23, l01, l23;
            asm("cvt.rn.bf16x2.f32 %0, %1, %2;" : "=r"(h01) : "f"(v.y), "f"(v.x));
            asm("cvt.rn.bf16x2.f32 %0, %1, %2;" : "=r"(h23) : "f"(v.w), "f"(v.z));
            float l0 = v.x - __uint_as_float(h01 << 16);
            float l1 = v.y - __uint_as_float(h01 & 0xffff0000u);
            float l2 = v.z - __uint_as_float(h23 << 16);
            float l3 = v.w - __uint_as_float(h23 & 0xffff0000u);
            asm("cvt.rn.bf16x2.f32 %0, %1, %2;" : "=r"(l01) : "f"(l1), "f"(l0));
            asm("cvt.rn.bf16x2.f32 %0, %1, %2;" : "=r"(l23) : "f"(l3), "f"(l2));
            int g  = fi128 >> 6;
            int fi = fi128 & 63;
            uint32_t off = ((uint32_t)(fi * 128 + p4 * 2)) ^ SWZ_ROW(fi);
            char* base = Ab + g * 16384 + off;
            *(uint2*)base          = make_uint2(h01, h23);
            *(uint2*)(base + 8192) = make_uint2(l01, l23);
        }
    };

    // ---------- per-lane ldmatrix address components ----------
    const int q  = lane >> 3;
    const int r8 = lane & 7;
    // A via ldmatrix.trans from [fi][p]: lane addresses source row fi, col = m block
    const uint32_t a_kq  = (uint32_t)((q >> 1) * 8 + r8);            // fi within k16 block
    const uint32_t a_off = a_kq * 128 +
        (((uint32_t)(warp_m * 32 + (q & 1) * 16)) ^ SWZ_ROW(a_kq));  // + kk*2048 per step
    // B: non-trans from [f][fi]
    const uint32_t b_sw   = SWZ_ROW(r8);
    const uint32_t b_colq = (uint32_t)((q & 1) * 16);
    uint32_t b_rt[2];
    #pragma unroll
    for (int u = 0; u < 2; u++)
        b_rt[u] = (uint32_t)((warp_n * 32 + (2 * u + (q >> 1)) * 8 + r8) * 128);

    float con[8][4][4];
    #pragma unroll
    for (int g = 0; g < 8; g++)
        #pragma unroll
        for (int nt = 0; nt < 4; nt++)
            #pragma unroll
            for (int k = 0; k < 4; k++) con[g][nt][k] = 0.0f;

    // ---------- prologue ----------
    load_stage(0, 0); cp_commit();
    load_stage(1, 1); cp_commit();
    asm volatile("cp.async.wait_group 1;\n");
    __syncthreads();
    convert(0);
    __syncthreads();

    // ---------- pipelined stage loop (4 stages x 2 groups) ----------
    #pragma unroll
    for (int s = 0; s < 4; s++) {
        const int buf = s & 1;
        const uint32_t Abuf = sb + OFF_A + buf * 32768;
        const uint32_t Bbuf = sb + OFF_B + buf * 32768;
        #pragma unroll
        for (int gg = 0; gg < 2; gg++) {
            const int g = 2 * s + gg;
            const uint32_t Ah = Abuf + gg * 16384, Al = Ah + 8192;
            const uint32_t Bh = Bbuf + gg * 16384, Bl = Bh + 8192;
            #pragma unroll
            for (int kk = 0; kk < 4; kk++) {
                uint32_t ah[4], al[4], bh[8], bl[8];
                LDSM4T(ah, Ah + a_off + kk * 2048);
                LDSM4T(al, Al + a_off + kk * 2048);
                uint32_t bcol = ((uint32_t)(kk * 32) + b_colq) ^ b_sw;
                LDSM4(&bh[0], Bh + b_rt[0] + bcol);
                LDSM4(&bh[4], Bh + b_rt[1] + bcol);
                LDSM4(&bl[0], Bl + b_rt[0] + bcol);
                LDSM4(&bl[4], Bl + b_rt[1] + bcol);
                #pragma unroll
                for (int nt = 0; nt < 4; nt++) {
                    MMA(con[g][nt], ah, &bh[nt * 2]);
                    MMA(con[g][nt], ah, &bl[nt * 2]);
                    MMA(con[g][nt], al, &bh[nt * 2]);
                }
            }
        }
        if (s < 3) {
            asm volatile("cp.async.wait_group 0;\n");
            __syncthreads();                       // stage s+1 data landed; all warps past mma(s)
            if (s < 2) { load_stage(s + 2, buf); cp_commit(); }   // overlaps convert below
            convert((s + 1) & 1);
            __syncthreads();
        }
    }

    // ================= routing epilogue =================
    float* sbuf = (float*)smem;                       // [2][64][36] = 18KB (XR region, dead)
    float* abuf = (float*)(smem + 2 * 64 * 36 * 4);   // [64][9]
    const int r0 = warp_m * 16 + (lane >> 2);         // thread's first row (position)

    // Gram matrix S[g][g'] per row, partial over this warp's 8 f-cols
    #pragma unroll
    for (int rr = 0; rr < 2; rr++) {
        float S[36];
        int idx = 0;
        #pragma unroll
        for (int a = 0; a < 8; a++) {
            #pragma unroll
            for (int c = a; c < 8; c++, idx++) {
                float acc = 0.0f;
                #pragma unroll
                for (int nt = 0; nt < 4; nt++) {
                    acc = fmaf(con[a][nt][2 * rr],     con[c][nt][2 * rr],     acc);
                    acc = fmaf(con[a][nt][2 * rr + 1], con[c][nt][2 * rr + 1], acc);
                }
                S[idx] = acc;
            }
        }
        #pragma unroll
        for (int i = 0; i < 36; i++) {
            S[i] += __shfl_xor_sync(0xffffffffu, S[i], 1);
            S[i] += __shfl_xor_sync(0xffffffffu, S[i], 2);
        }
        int row = r0 + rr * 8;
        for (int i = (lane & 3); i < 36; i += 4)
            sbuf[(warp_n * 64 + row) * 36 + i] = S[i];
    }
    __syncthreads();

    // per-position recurrence (threads 0..63)
    if (tid < 64) {
        float Sf[36];
        #pragma unroll
        for (int i = 0; i < 36; i++)
            Sf[i] = sbuf[tid * 36 + i] + sbuf[(64 + tid) * 36 + i];
        auto SM = [&](int a, int c) -> float {
            int lo = a < c ? a : c, hi = a < c ? c : a;
            return Sf[lo * 8 - (lo * (lo + 1)) / 2 + hi];
        };
        float beta[8];
        #pragma unroll
        for (int g = 0; g < 8; g++) {          // iter 0: alpha = 0.5
            float rs = 0.0f;
            #pragma unroll
            for (int gp = 0; gp < 8; gp++) rs += SM(g, gp);
            beta[g] = 0.5f * rs;
        }
        float alpha[8];
        #pragma unroll
        for (int g = 0; g < 8; g++) alpha[g] = sigmoidf_(beta[g]);
        #pragma unroll
        for (int g = 0; g < 8; g++) {          // iter 1
            float acc = 0.0f;
            #pragma unroll
            for (int gp = 0; gp < 8; gp++) acc = fmaf(alpha[gp], SM(gp, g), acc);
            beta[g] += acc;
        }
        #pragma unroll
        for (int g = 0; g < 8; g++) abuf[tid * 9 + g] = sigmoidf_(beta[g]);
    }
    __syncthreads();

    // v = sum_g alpha_g * con_g
    float a0[8], a1[8];
    #pragma unroll
    for (int g = 0; g < 8; g++) {
        a0[g] = abuf[r0 * 9 + g];
        a1[g] = abuf[(r0 + 8) * 9 + g];
    }
    float v[4][4];
    #pragma unroll
    for (int nt = 0; nt < 4; nt++)
        #pragma unroll
        for (int k = 0; k < 4; k++) v[nt][k] = 0.0f;
    #pragma unroll
    for (int g = 0; g < 8; g++)
        #pragma unroll
        for (int nt = 0; nt < 4; nt++) {
            v[nt][0] = fmaf(a0[g], con[g][nt][0], v[nt][0]);
            v[nt][1] = fmaf(a0[g], con[g][nt][1], v[nt][1]);
            v[nt][2] = fmaf(a1[g], con[g][nt][2], v[nt][2]);
            v[nt][3] = fmaf(a1[g], con[g][nt][3], v[nt][3]);
        }

    // transpose through smem for coalesced stores
    float* vbuf = (float*)(smem + OFF_A);             // [64 f][65] (A region, dead)
    const int cb = 2 * (lane & 3);
    #pragma unroll
    for (int nt = 0; nt < 4; nt++) {
        int f = warp_n * 32 + nt * 8 + cb;
        vbuf[f * 65 + r0]           = v[nt][0];
        vbuf[(f + 1) * 65 + r0]     = v[nt][1];
        vbuf[f * 65 + r0 + 8]       = v[nt][2];
        vbuf[(f + 1) * 65 + r0 + 8] = v[nt][3];
    }
    __syncthreads();

    float* ob = out + (size_t)b * 64 * HW + hw0;
    #pragma unroll
    for (int c = 0; c < 16; c++) {
        int flat = tid + 256 * c;                     // 0..4095
        int f = flat >> 6, p = flat & 63;
        ob[(size_t)f * HW + p] = vbuf[f * 65 + p] + __ldg(&bias[f]);
    }
}

extern "C" void kernel_launch(void* const* d_in, const int* in_sizes, int n_in,
                              void* d_out, int out_size) {
    const float* x    = (const float*)d_in[0];
    const float* w    = (const float*)d_in[1];
    const float* bias = (const float*)d_in[2];
    float* out = (float*)d_out;

    prep_kernel<<<64, 256>>>(w);

    cudaFuncSetAttribute(routing_kernel,
                         cudaFuncAttributeMaxDynamicSharedMemorySize, SMEM_TOTAL);
    routing_kernel<<<1024, 256, SMEM_TOTAL>>>(x, bias, out);
}